// round 1
// baseline (speedup 1.0000x reference)
#include <cuda_runtime.h>
#include <cuda_bf16.h>
#include <math.h>

// Problem: b=2, f=8, c=64, h=w=256
//   k_sum[bf,c]   = sum_{hw} nbr[bf,c,hw]
//   out[bf,hw]    = sigmoid( sum_c ref[bf,c,hw] * k_sum[bf,c] )
// Pure HBM-streaming: 2x 2.147GB reads, 4.2MB write.

#define BF     16          // b*f
#define C      64
#define HW     65536       // 256*256
#define HW4    16384       // HW / 4 (float4 units)

// Scratch for channel sums (BF*C = 1024 floats). No zeroing needed: each
// block in k1 writes its own element exactly once.
__device__ float g_ksum[BF * C];

// ---------------------------------------------------------------------------
// Kernel 1: per-channel-plane reduction. One block per (bf,c) plane (256 KB).
// 256 threads * 64 float4 loads each, fully coalesced.
// ---------------------------------------------------------------------------
__global__ __launch_bounds__(256) void ksum_kernel(const float* __restrict__ nbr) {
    const int ch = blockIdx.x;                       // 0..1023 == bf*64 + c
    const float4* __restrict__ p =
        reinterpret_cast<const float4*>(nbr + (size_t)ch * HW);

    float s = 0.0f;
    #pragma unroll 8
    for (int i = threadIdx.x; i < HW4; i += 256) {
        float4 v = p[i];
        s += (v.x + v.y) + (v.z + v.w);
    }

    // intra-warp reduce
    #pragma unroll
    for (int off = 16; off > 0; off >>= 1)
        s += __shfl_xor_sync(0xffffffffu, s, off);

    __shared__ float warp_sums[8];
    const int lane = threadIdx.x & 31;
    const int wid  = threadIdx.x >> 5;
    if (lane == 0) warp_sums[wid] = s;
    __syncthreads();

    if (wid == 0) {
        float t = (lane < 8) ? warp_sums[lane] : 0.0f;
        #pragma unroll
        for (int off = 4; off > 0; off >>= 1)
            t += __shfl_xor_sync(0xffffffffu, t, off);
        if (lane == 0) g_ksum[ch] = t;
    }
}

// ---------------------------------------------------------------------------
// Kernel 2: weighted channel contraction + sigmoid.
// One float4 (4 pixels) per thread. 64 blocks per bf slice (16384 float4 /
// 256 threads), so each block has a single bf -> k_sum broadcast via smem.
// The fully unrolled channel loop front-batches 64 independent LDG.128.
// ---------------------------------------------------------------------------
__global__ __launch_bounds__(256) void weight_kernel(const float* __restrict__ ref,
                                                     float* __restrict__ out) {
    const int bf   = blockIdx.x >> 6;                // 64 blocks per bf
    const int pix4 = ((blockIdx.x & 63) << 8) + threadIdx.x;   // 0..16383

    __shared__ float sk[C];
    if (threadIdx.x < C) sk[threadIdx.x] = g_ksum[bf * C + threadIdx.x];
    __syncthreads();

    const float4* __restrict__ base =
        reinterpret_cast<const float4*>(ref) + (size_t)bf * C * HW4 + pix4;

    float ax = 0.0f, ay = 0.0f, az = 0.0f, aw = 0.0f;
    #pragma unroll
    for (int c = 0; c < C; c++) {
        float4 v = base[(size_t)c * HW4];
        float  k = sk[c];
        ax = fmaf(v.x, k, ax);
        ay = fmaf(v.y, k, ay);
        az = fmaf(v.z, k, az);
        aw = fmaf(v.w, k, aw);
    }

    float4 r;
    r.x = 1.0f / (1.0f + expf(-ax));
    r.y = 1.0f / (1.0f + expf(-ay));
    r.z = 1.0f / (1.0f + expf(-az));
    r.w = 1.0f / (1.0f + expf(-aw));

    reinterpret_cast<float4*>(out)[(size_t)bf * HW4 + pix4] = r;
}

// ---------------------------------------------------------------------------
extern "C" void kernel_launch(void* const* d_in, const int* in_sizes, int n_in,
                              void* d_out, int out_size) {
    const float* nbr = (const float*)d_in[0];
    const float* ref = (const float*)d_in[1];
    float* out = (float*)d_out;

    ksum_kernel<<<BF * C, 256>>>(nbr);
    weight_kernel<<<BF * HW4 / 256, 256>>>(ref, out);
}

// round 2
// speedup vs baseline: 1.0293x; 1.0293x over previous
#include <cuda_runtime.h>
#include <cuda_bf16.h>
#include <math.h>

// Problem: b=2, f=8, c=64, h=w=256  (fp32)
//   k_sum[bf,c] = sum_{hw} nbr[bf,c,hw]
//   out[bf,hw]  = sigmoid( sum_c ref[bf,c,hw] * k_sum[bf,c] )
// HBM streaming: 2 x 268MB reads + 4MB write. Floor ~77-81us.

#define BF     16          // b*f
#define C      64
#define HW     65536       // 256*256
#define HW4    16384       // HW / 4 (float4 units)

__device__ float g_ksum[BF * C];

// ---------------------------------------------------------------------------
// Kernel 1: per-channel-plane reduction. One block per (bf,c) plane (256 KB
// contiguous). 256 threads * 64 float4 streaming loads each.
// ---------------------------------------------------------------------------
__global__ __launch_bounds__(256) void ksum_kernel(const float* __restrict__ nbr) {
    const int ch = blockIdx.x;                       // 0..1023 == bf*64 + c
    const float4* __restrict__ p =
        reinterpret_cast<const float4*>(nbr + (size_t)ch * HW);

    float s = 0.0f;
    #pragma unroll 8
    for (int i = threadIdx.x; i < HW4; i += 256) {
        float4 v = __ldcs(p + i);
        s += (v.x + v.y) + (v.z + v.w);
    }

    #pragma unroll
    for (int off = 16; off > 0; off >>= 1)
        s += __shfl_xor_sync(0xffffffffu, s, off);

    __shared__ float warp_sums[8];
    const int lane = threadIdx.x & 31;
    const int wid  = threadIdx.x >> 5;
    if (lane == 0) warp_sums[wid] = s;
    __syncthreads();

    if (wid == 0) {
        float t = (lane < 8) ? warp_sums[lane] : 0.0f;
        #pragma unroll
        for (int off = 4; off > 0; off >>= 1)
            t += __shfl_xor_sync(0xffffffffu, t, off);
        if (lane == 0) g_ksum[ch] = t;
    }
}

// ---------------------------------------------------------------------------
// Kernel 2: weighted channel contraction + sigmoid.
// Each block owns a 512-float4 (8 KB) pixel window; per channel step it
// streams 8 KB contiguous (two coalesced LDG.128 per thread at [t], [t+256]).
// 512 blocks = 32 per bf slice -> single k_sum broadcast per block.
// ---------------------------------------------------------------------------
__global__ __launch_bounds__(256) void weight_kernel(const float* __restrict__ ref,
                                                     float* __restrict__ out) {
    const int bf  = blockIdx.x >> 5;                     // 32 blocks per bf
    const int win = (blockIdx.x & 31) << 9;              // window base (float4)
    const int p0  = win + threadIdx.x;
    const int p1  = p0 + 256;

    __shared__ float sk[C];
    if (threadIdx.x < C) sk[threadIdx.x] = g_ksum[bf * C + threadIdx.x];
    __syncthreads();

    const float4* __restrict__ base =
        reinterpret_cast<const float4*>(ref) + (size_t)bf * C * HW4;

    float a0x = 0.f, a0y = 0.f, a0z = 0.f, a0w = 0.f;
    float a1x = 0.f, a1y = 0.f, a1z = 0.f, a1w = 0.f;

    #pragma unroll
    for (int c = 0; c < C; c++) {
        const float4* chp = base + (size_t)c * HW4;
        float4 v0 = __ldcs(chp + p0);
        float4 v1 = __ldcs(chp + p1);
        float  k  = sk[c];
        a0x = fmaf(v0.x, k, a0x);
        a0y = fmaf(v0.y, k, a0y);
        a0z = fmaf(v0.z, k, a0z);
        a0w = fmaf(v0.w, k, a0w);
        a1x = fmaf(v1.x, k, a1x);
        a1y = fmaf(v1.y, k, a1y);
        a1z = fmaf(v1.z, k, a1z);
        a1w = fmaf(v1.w, k, a1w);
    }

    float4 r0, r1;
    r0.x = 1.0f / (1.0f + expf(-a0x));
    r0.y = 1.0f / (1.0f + expf(-a0y));
    r0.z = 1.0f / (1.0f + expf(-a0z));
    r0.w = 1.0f / (1.0f + expf(-a0w));
    r1.x = 1.0f / (1.0f + expf(-a1x));
    r1.y = 1.0f / (1.0f + expf(-a1y));
    r1.z = 1.0f / (1.0f + expf(-a1z));
    r1.w = 1.0f / (1.0f + expf(-a1w));

    float4* o = reinterpret_cast<float4*>(out) + (size_t)bf * HW4;
    o[p0] = r0;
    o[p1] = r1;
}

// ---------------------------------------------------------------------------
extern "C" void kernel_launch(void* const* d_in, const int* in_sizes, int n_in,
                              void* d_out, int out_size) {
    const float* nbr = (const float*)d_in[0];
    const float* ref = (const float*)d_in[1];
    float* out = (float*)d_out;

    ksum_kernel<<<BF * C, 256>>>(nbr);
    weight_kernel<<<BF * HW4 / 512, 256>>>(ref, out);
}